// round 5
// baseline (speedup 1.0000x reference)
#include <cuda_runtime.h>
#include <cuda_bf16.h>

#define TICKS   1000
#define TPAD    1024        // TICKS rounded up to 32 — sim chunks read the pad
#define NTAPS   49
#define KW      7
#define OUT_CH  128
#define MAXD    14          // 6 + min(stride,8)
#define MAXC    (MAXD*MAXD) // 196

// ---- scratch (no allocations allowed) ----
// Transposed layout: hist[cls][t]. Row stride 4000B (16B multiple) and
// __align__(16) make the float4-over-t loads in sim Phase B legal.
__device__ __align__(16) float d_hist[MAXC * TICKS];

__device__ __forceinline__ int imin(int a, int b) { return a < b ? a : b; }

// ------------------------------------------------------------------
// 1) event scatter: one global RED.F32.ADD per event into hist[cls][t].
//    Class lookup via 16KB shared LUT (absorbs all stride logic, no
//    divergent hot/cold split). RED has no return -> no scoreboard stalls.
//    spike_values are 1.0f so per-slot sums are exact integers: atomic
//    ordering cannot perturb results.
// ------------------------------------------------------------------
__global__ void __launch_bounds__(1024) scatter_kernel(
    const int* __restrict__ tk, const int* __restrict__ xs,
    const int* __restrict__ ys, const float* __restrict__ vs,
    const int* __restrict__ sp, int n)
{
    __shared__ unsigned char lut[128 * 128];
    const int stride = *sp;
    const int D = 6 + imin(stride, 8);

    // build class LUT: lut[y*128+x] = cy*D + cx  (16 iters/thread)
    for (int i = threadIdx.x; i < 128 * 128; i += blockDim.x) {
        int y = i >> 7, x = i & 127;
        int cx = (x < 6) ? x : 6 + imin(x % stride, 7);
        int cy = (y < 6) ? y : 6 + imin(y % stride, 7);
        lut[i] = (unsigned char)(cy * D + cx);
    }
    __syncthreads();

    const int tid = blockIdx.x * blockDim.x + threadIdx.x;
    const int nth = gridDim.x * blockDim.x;

    auto proc = [&](int t, int x, int y, float v) {
        int cls = lut[(y << 7) | x];
        atomicAdd(&d_hist[cls * TICKS + t], v);   // -> RED.E.ADD.F32 (no return)
    };

    const int n4 = n >> 2;
    const int4*   t4 = reinterpret_cast<const int4*>(tk);
    const int4*   x4 = reinterpret_cast<const int4*>(xs);
    const int4*   y4 = reinterpret_cast<const int4*>(ys);
    const float4* v4 = reinterpret_cast<const float4*>(vs);

    for (int i = tid; i < n4; i += nth) {
        int4   a = t4[i];
        int4   b = x4[i];
        int4   c = y4[i];
        float4 w = v4[i];
        proc(a.x, b.x, c.x, w.x);
        proc(a.y, b.y, c.y, w.y);
        proc(a.z, b.z, c.z, w.z);
        proc(a.w, b.w, c.w, w.w);
    }
    for (int i = (n4 << 2) + tid; i < n; i += nth)
        proc(tk[i], xs[i], ys[i], vs[i]);
}

// ------------------------------------------------------------------
// 2) fused drive + Izhikevich sim. One block per channel.
//    Phase A: class weights (shared).
//    Phase B: delayed drive g[t] = dot(wc, hist[:, t-1]) into sg[],
//             float4-vectorized over t (cls accumulation order unchanged
//             -> bit-identical to the passing R4 kernel).
//    Phase C: warp 0 runs the serial neuron recurrence (byte-identical
//             arithmetic to R4; stores guarded, TICKS % 32 != 0).
// ------------------------------------------------------------------
__global__ void __launch_bounds__(128) sim_kernel(
    const float* __restrict__ w, const int* __restrict__ sp,
    float* __restrict__ out)
{
    __shared__ float wc[MAXC];
    __shared__ float sg[TPAD + 4];   // +4: chunk t0=996 writes sg[997..1000]

    const int c   = blockIdx.x;
    const int tid = threadIdx.x;
    const int stride = *sp;
    const int D = 6 + imin(stride, 8);
    const int C = D * D;

    // ---- Phase A: class weights for this channel ----
    for (int cls = tid; cls < C; cls += blockDim.x) {
        const int cy = cls / D, cx = cls % D;
        int sx, lx, sy, ly;
        if (cx < 6) { sx = cx % stride; lx = cx; } else { sx = cx - 6; lx = 6; }
        if (cy < 6) { sy = cy % stride; ly = cy; } else { sy = cy - 6; ly = 6; }
        float acc = 0.f;
        for (int ky = sy; ky <= ly; ky += stride)
            for (int kx = sx; kx <= lx; kx += stride)
                acc += w[c * NTAPS + ky * KW + kx];
        wc[cls] = acc;
    }
    // zero sg (pad included); Phase B overwrites sg[1..1000]
    for (int i = tid; i < TPAD + 4; i += blockDim.x) sg[i] = 0.f;
    __syncthreads();

    // ---- Phase B: g[t] = dot(wc, hist[:, t-1]); g[0] stays 0 ----
    for (int ch = tid; ch < TICKS / 4; ch += blockDim.x) {
        const int t0 = ch * 4;                      // 16B-aligned in each row
        float4 acc = make_float4(0.f, 0.f, 0.f, 0.f);
        const char* base = reinterpret_cast<const char*>(d_hist) + (size_t)t0 * 4;
        for (int cls = 0; cls < C; ++cls) {
            float  wcv = wc[cls];
            float4 hv  = __ldg(reinterpret_cast<const float4*>(
                                   base + (size_t)cls * (TICKS * 4)));
            acc.x = fmaf(wcv, hv.x, acc.x);
            acc.y = fmaf(wcv, hv.y, acc.y);
            acc.z = fmaf(wcv, hv.z, acc.z);
            acc.w = fmaf(wcv, hv.w, acc.w);
        }
        sg[t0 + 1] = acc.x;                         // 1-tick synaptic delay
        sg[t0 + 2] = acc.y;
        sg[t0 + 3] = acc.z;
        sg[t0 + 4] = acc.w;
    }
    __syncthreads();

    // ---- Phase C: serial sim, warp 0 only (arithmetic unchanged) ----
    if (tid >= 32) return;
    const int lane = tid;

    float* __restrict__ ospk = out + c * TICKS;
    float* __restrict__ ovtr = out + OUT_CH * TICKS + c * TICKS;

    const float decay = 0.9f;                        // 1 - dt/tau_fall
    const float h     = (float)(0.001 / 150.0);      // dt / C
    const float Kp = 1.2f, VR = -75.f, VT = -45.f;
    const float AP = 0.01f, BP = 5.f, VP = 50.f;
    const float DP = 130.f, VRS = -56.f, IIN = 350.f, DT = 0.001f;

    float v = VR, u = 0.f, S = 0.f;

    for (int t0 = 0; t0 < TICKS; t0 += 32) {
        float keepv = 0.f, keeps = 0.f;
        #pragma unroll
        for (int i = 0; i < 32; ++i) {
            float gt = sg[t0 + i];                   // pad ticks harmless
            S = S * decay + gt;                      // summed synapse state
            float I = IIN + S;                       // I_bias = 0
            v = v + (Kp * (v - VR) * (v - VT) - u + I) * h;
            u = u + AP * (BP * (v - VR) - u) * DT;   // uses pre-reset v
            bool sp = v >= VP;
            float spf = sp ? 1.f : 0.f;
            if (sp) { v = VRS; u = u + DP; }
            keepv = (lane == i) ? v   : keepv;       // register-keep, off chain
            keeps = (lane == i) ? spf : keeps;
        }
        int t = t0 + lane;
        if (t < TICKS) {                             // guard: 1000 % 32 != 0
            ospk[t] = keeps;                         // coalesced per chunk
            ovtr[t] = keepv;
        }
    }
}

// ------------------------------------------------------------------
extern "C" void kernel_launch(void* const* d_in, const int* in_sizes, int n_in,
                              void* d_out, int out_size)
{
    const int*   tk = (const int*)  d_in[0];   // spike_ticks
    const int*   xs = (const int*)  d_in[1];   // spike_x
    const int*   ys = (const int*)  d_in[2];   // spike_y
    const float* vs = (const float*)d_in[3];   // spike_values
    const float* w  = (const float*)d_in[4];   // weights [128,49]
    const int*   sp = (const int*)  d_in[5];   // stride
    const int    n  = in_sizes[0];

    void* hist_ptr = nullptr;
    cudaGetSymbolAddress(&hist_ptr, d_hist);
    cudaMemsetAsync(hist_ptr, 0, sizeof(float) * MAXC * TICKS);   // memset node

    scatter_kernel<<<148, 1024>>>(tk, xs, ys, vs, sp, n);
    sim_kernel<<<OUT_CH, 128>>>(w, sp, (float*)d_out);
}

// round 6
// speedup vs baseline: 1.0489x; 1.0489x over previous
#include <cuda_runtime.h>
#include <cuda_bf16.h>

#define TICKS   1000
#define TPAD    1024        // TICKS rounded up to 32 — sim chunks read the pad
#define NTAPS   49
#define KW      7
#define OUT_CH  128
#define MAXD    14          // 6 + min(stride,8)
#define MAXC    (MAXD*MAXD) // 196

// ---- scratch (no allocations allowed) ----
// Transposed layout: hist[cls][t]. Row stride 4000B (16B multiple) and
// __align__(16) make the float4-over-t loads in sim Phase B legal.
__device__ __align__(16) float d_hist[MAXC * TICKS];

__device__ __forceinline__ int imin(int a, int b) { return a < b ? a : b; }

// ------------------------------------------------------------------
// 1) event scatter: one global RED.F32.ADD per event into hist[cls][t].
//    Class lookup via 16KB shared LUT (absorbs all stride logic, no
//    divergent hot/cold split). RED has no return -> no scoreboard stalls.
//    spike_values are 1.0f so per-slot sums are exact integers: atomic
//    ordering cannot perturb results.
// ------------------------------------------------------------------
__global__ void __launch_bounds__(1024) scatter_kernel(
    const int* __restrict__ tk, const int* __restrict__ xs,
    const int* __restrict__ ys, const float* __restrict__ vs,
    const int* __restrict__ sp, int n)
{
    __shared__ unsigned char lut[128 * 128];
    const int stride = *sp;
    const int D = 6 + imin(stride, 8);

    // build class LUT: lut[y*128+x] = cy*D + cx  (16 iters/thread)
    for (int i = threadIdx.x; i < 128 * 128; i += blockDim.x) {
        int y = i >> 7, x = i & 127;
        int cx = (x < 6) ? x : 6 + imin(x % stride, 7);
        int cy = (y < 6) ? y : 6 + imin(y % stride, 7);
        lut[i] = (unsigned char)(cy * D + cx);
    }
    __syncthreads();

    const int tid = blockIdx.x * blockDim.x + threadIdx.x;
    const int nth = gridDim.x * blockDim.x;

    auto proc = [&](int t, int x, int y, float v) {
        int cls = lut[(y << 7) | x];
        atomicAdd(&d_hist[cls * TICKS + t], v);   // -> RED.E.ADD.F32 (no return)
    };

    const int n4 = n >> 2;
    const int4*   t4 = reinterpret_cast<const int4*>(tk);
    const int4*   x4 = reinterpret_cast<const int4*>(xs);
    const int4*   y4 = reinterpret_cast<const int4*>(ys);
    const float4* v4 = reinterpret_cast<const float4*>(vs);

    for (int i = tid; i < n4; i += nth) {
        int4   a = t4[i];
        int4   b = x4[i];
        int4   c = y4[i];
        float4 w = v4[i];
        proc(a.x, b.x, c.x, w.x);
        proc(a.y, b.y, c.y, w.y);
        proc(a.z, b.z, c.z, w.z);
        proc(a.w, b.w, c.w, w.w);
    }
    for (int i = (n4 << 2) + tid; i < n; i += nth)
        proc(tk[i], xs[i], ys[i], vs[i]);
}

// ------------------------------------------------------------------
// 2) fused drive + Izhikevich sim. One block per channel.
//    Phase A: class weights (shared).
//    Phase B: delayed drive g[t] = dot(wc, hist[:, t-1]) into sg[],
//             float4 over t; cls loop unrolled x8 so 8 LDG.128 batch up
//             (R5 regression: non-unrolled loop exposed full L2 latency
//             per iteration). cls accumulation order unchanged ->
//             bit-identical g.
//    Phase C: warp 0 runs the serial neuron recurrence (byte-identical
//             arithmetic; stores guarded, TICKS % 32 != 0).
// ------------------------------------------------------------------
__global__ void __launch_bounds__(128) sim_kernel(
    const float* __restrict__ w, const int* __restrict__ sp,
    float* __restrict__ out)
{
    __shared__ float wc[MAXC];
    __shared__ float sg[TPAD + 4];   // +4: chunk t0=996 writes sg[997..1000]

    const int c   = blockIdx.x;
    const int tid = threadIdx.x;
    const int stride = *sp;
    const int D = 6 + imin(stride, 8);
    const int C = D * D;

    // ---- Phase A: class weights for this channel ----
    for (int cls = tid; cls < C; cls += blockDim.x) {
        const int cy = cls / D, cx = cls % D;
        int sx, lx, sy, ly;
        if (cx < 6) { sx = cx % stride; lx = cx; } else { sx = cx - 6; lx = 6; }
        if (cy < 6) { sy = cy % stride; ly = cy; } else { sy = cy - 6; ly = 6; }
        float acc = 0.f;
        for (int ky = sy; ky <= ly; ky += stride)
            for (int kx = sx; kx <= lx; kx += stride)
                acc += w[c * NTAPS + ky * KW + kx];
        wc[cls] = acc;
    }
    // zero sg (pad included); Phase B overwrites sg[1..1000]
    for (int i = tid; i < TPAD + 4; i += blockDim.x) sg[i] = 0.f;
    __syncthreads();

    // ---- Phase B: g[t] = dot(wc, hist[:, t-1]); g[0] stays 0 ----
    for (int ch = tid; ch < TICKS / 4; ch += blockDim.x) {
        const int t0 = ch * 4;                      // 16B-aligned in each row
        float4 acc = make_float4(0.f, 0.f, 0.f, 0.f);
        const char* base = reinterpret_cast<const char*>(d_hist) + (size_t)t0 * 4;
        #pragma unroll 8
        for (int cls = 0; cls < C; ++cls) {
            float  wcv = wc[cls];
            float4 hv  = __ldg(reinterpret_cast<const float4*>(
                                   base + (size_t)cls * (TICKS * 4)));
            acc.x = fmaf(wcv, hv.x, acc.x);
            acc.y = fmaf(wcv, hv.y, acc.y);
            acc.z = fmaf(wcv, hv.z, acc.z);
            acc.w = fmaf(wcv, hv.w, acc.w);
        }
        sg[t0 + 1] = acc.x;                         // 1-tick synaptic delay
        sg[t0 + 2] = acc.y;
        sg[t0 + 3] = acc.z;
        sg[t0 + 4] = acc.w;
    }
    __syncthreads();

    // ---- Phase C: serial sim, warp 0 only (arithmetic unchanged) ----
    if (tid >= 32) return;
    const int lane = tid;

    float* __restrict__ ospk = out + c * TICKS;
    float* __restrict__ ovtr = out + OUT_CH * TICKS + c * TICKS;

    const float decay = 0.9f;                        // 1 - dt/tau_fall
    const float h     = (float)(0.001 / 150.0);      // dt / C
    const float Kp = 1.2f, VR = -75.f, VT = -45.f;
    const float AP = 0.01f, BP = 5.f, VP = 50.f;
    const float DP = 130.f, VRS = -56.f, IIN = 350.f, DT = 0.001f;

    float v = VR, u = 0.f, S = 0.f;

    for (int t0 = 0; t0 < TICKS; t0 += 32) {
        float keepv = 0.f, keeps = 0.f;
        #pragma unroll
        for (int i = 0; i < 32; ++i) {
            float gt = sg[t0 + i];                   // pad ticks harmless
            S = S * decay + gt;                      // summed synapse state
            float I = IIN + S;                       // I_bias = 0
            v = v + (Kp * (v - VR) * (v - VT) - u + I) * h;
            u = u + AP * (BP * (v - VR) - u) * DT;   // uses pre-reset v
            bool sp = v >= VP;
            float spf = sp ? 1.f : 0.f;
            if (sp) { v = VRS; u = u + DP; }
            keepv = (lane == i) ? v   : keepv;       // register-keep, off chain
            keeps = (lane == i) ? spf : keeps;
        }
        int t = t0 + lane;
        if (t < TICKS) {                             // guard: 1000 % 32 != 0
            ospk[t] = keeps;                         // coalesced per chunk
            ovtr[t] = keepv;
        }
    }
}

// ------------------------------------------------------------------
extern "C" void kernel_launch(void* const* d_in, const int* in_sizes, int n_in,
                              void* d_out, int out_size)
{
    const int*   tk = (const int*)  d_in[0];   // spike_ticks
    const int*   xs = (const int*)  d_in[1];   // spike_x
    const int*   ys = (const int*)  d_in[2];   // spike_y
    const float* vs = (const float*)d_in[3];   // spike_values
    const float* w  = (const float*)d_in[4];   // weights [128,49]
    const int*   sp = (const int*)  d_in[5];   // stride
    const int    n  = in_sizes[0];

    void* hist_ptr = nullptr;
    cudaGetSymbolAddress(&hist_ptr, d_hist);
    cudaMemsetAsync(hist_ptr, 0, sizeof(float) * MAXC * TICKS);   // memset node

    scatter_kernel<<<296, 1024>>>(tk, xs, ys, vs, sp, n);   // 2 CTAs/SM
    sim_kernel<<<OUT_CH, 128>>>(w, sp, (float*)d_out);
}

// round 7
// speedup vs baseline: 1.3395x; 1.2770x over previous
#include <cuda_runtime.h>
#include <cuda_bf16.h>

#define TICKS   1000
#define TPAD    1024        // TICKS rounded up to 32 — sim chunks read the pad
#define NTAPS   49
#define KW      7
#define OUT_CH  128
#define MAXD    14          // 6 + min(stride,8)
#define MAXC    (MAXD*MAXD) // 196

// ---- scratch (no allocations allowed) ----
// Transposed layout: hist[cls][t] -> warp-coalesced loads over t in sim Phase B.
__device__ __align__(16) float d_hist[MAXC * TICKS];

__device__ __forceinline__ int imin(int a, int b) { return a < b ? a : b; }

// ------------------------------------------------------------------
// 1) event scatter: one global RED.F32.ADD per event into hist[cls][t].
//    Class computed arithmetically (warp-uniform stride==2 fast path) —
//    no LUT, no LDS on the LSU pipe. RED has no return -> no scoreboard
//    stalls. spike_values are 1.0f so per-slot sums are exact integers:
//    atomic ordering cannot perturb results.
// ------------------------------------------------------------------
__global__ void __launch_bounds__(1024) scatter_kernel(
    const int* __restrict__ tk, const int* __restrict__ xs,
    const int* __restrict__ ys, const float* __restrict__ vs,
    const int* __restrict__ sp, int n)
{
    const int stride = *sp;
    const int D = 6 + imin(stride, 8);

    const int tid = blockIdx.x * blockDim.x + threadIdx.x;
    const int nth = gridDim.x * blockDim.x;

    auto proc = [&](int t, int x, int y, float v) {
        int cx, cy;
        if (stride == 2) {                       // warp-uniform branch
            cx = (x < 6) ? x : (6 + (x & 1));
            cy = (y < 6) ? y : (6 + (y & 1));
        } else {
            cx = (x < 6) ? x : 6 + imin(x % stride, 7);
            cy = (y < 6) ? y : 6 + imin(y % stride, 7);
        }
        atomicAdd(&d_hist[(cy * D + cx) * TICKS + t], v);  // RED.E.ADD.F32
    };

    const int n4 = n >> 2;
    const int4*   t4 = reinterpret_cast<const int4*>(tk);
    const int4*   x4 = reinterpret_cast<const int4*>(xs);
    const int4*   y4 = reinterpret_cast<const int4*>(ys);
    const float4* v4 = reinterpret_cast<const float4*>(vs);

    for (int i = tid; i < n4; i += nth) {
        int4   a = t4[i];
        int4   b = x4[i];
        int4   c = y4[i];
        float4 w = v4[i];
        proc(a.x, b.x, c.x, w.x);
        proc(a.y, b.y, c.y, w.y);
        proc(a.z, b.z, c.z, w.z);
        proc(a.w, b.w, c.w, w.w);
    }
    for (int i = (n4 << 2) + tid; i < n; i += nth)
        proc(tk[i], xs[i], ys[i], vs[i]);
}

// ------------------------------------------------------------------
// 2) fused drive + Izhikevich sim. One 1024-thread block per channel.
//    Phase A: class weights (shared).
//    Phase B: ONE TICK PER THREAD — warp lanes read consecutive t of the
//             same hist row (coalesced LDG.32), 64 independent loads per
//             thread under unroll -> ~1us. Single sequential accumulator
//             over cls (same order as before -> bit-identical g).
//    Phase C: warp 0 runs the serial neuron recurrence (byte-identical
//             arithmetic; stores guarded, TICKS % 32 != 0).
// ------------------------------------------------------------------
__global__ void __launch_bounds__(1024) sim_kernel(
    const float* __restrict__ w, const int* __restrict__ sp,
    float* __restrict__ out)
{
    __shared__ float wc[MAXC];
    __shared__ float sg[TPAD + 4];

    const int c   = blockIdx.x;
    const int tid = threadIdx.x;
    const int stride = *sp;
    const int D = 6 + imin(stride, 8);
    const int C = D * D;

    // ---- Phase A: class weights for this channel ----
    if (tid < C) {
        const int cls = tid;
        const int cy = cls / D, cx = cls % D;
        int sx, lx, sy, ly;
        if (cx < 6) { sx = cx % stride; lx = cx; } else { sx = cx - 6; lx = 6; }
        if (cy < 6) { sy = cy % stride; ly = cy; } else { sy = cy - 6; ly = 6; }
        float acc = 0.f;
        for (int ky = sy; ky <= ly; ky += stride)
            for (int kx = sx; kx <= lx; kx += stride)
                acc += w[c * NTAPS + ky * KW + kx];
        wc[cls] = acc;
    }
    // zero sg (covers sg[0] and the pad)
    for (int i = tid; i < TPAD + 4; i += blockDim.x) sg[i] = 0.f;
    __syncthreads();

    // ---- Phase B: sg[t] = dot(wc, hist[:, t-1]) for t in [1, TICKS] ----
    if (tid >= 1 && tid <= TICKS) {
        const int tm1 = tid - 1;                  // source tick
        const float* __restrict__ hp = d_hist + tm1;
        float acc = 0.f;
        #pragma unroll 16
        for (int cls = 0; cls < C; ++cls)
            acc = fmaf(wc[cls], __ldg(&hp[cls * TICKS]), acc);
        sg[tid] = acc;                            // 1-tick synaptic delay
    }
    __syncthreads();

    // ---- Phase C: serial sim, warp 0 only (arithmetic unchanged) ----
    if (tid >= 32) return;
    const int lane = tid;

    float* __restrict__ ospk = out + c * TICKS;
    float* __restrict__ ovtr = out + OUT_CH * TICKS + c * TICKS;

    const float decay = 0.9f;                        // 1 - dt/tau_fall
    const float h     = (float)(0.001 / 150.0);      // dt / C
    const float Kp = 1.2f, VR = -75.f, VT = -45.f;
    const float AP = 0.01f, BP = 5.f, VP = 50.f;
    const float DP = 130.f, VRS = -56.f, IIN = 350.f, DT = 0.001f;

    float v = VR, u = 0.f, S = 0.f;

    for (int t0 = 0; t0 < TICKS; t0 += 32) {
        float keepv = 0.f, keeps = 0.f;
        #pragma unroll
        for (int i = 0; i < 32; ++i) {
            float gt = sg[t0 + i];                   // pad ticks harmless
            S = S * decay + gt;                      // summed synapse state
            float I = IIN + S;                       // I_bias = 0
            v = v + (Kp * (v - VR) * (v - VT) - u + I) * h;
            u = u + AP * (BP * (v - VR) - u) * DT;   // uses pre-reset v
            bool sp = v >= VP;
            float spf = sp ? 1.f : 0.f;
            if (sp) { v = VRS; u = u + DP; }
            keepv = (lane == i) ? v   : keepv;       // register-keep, off chain
            keeps = (lane == i) ? spf : keeps;
        }
        int t = t0 + lane;
        if (t < TICKS) {                             // guard: 1000 % 32 != 0
            ospk[t] = keeps;                         // coalesced per chunk
            ovtr[t] = keepv;
        }
    }
}

// ------------------------------------------------------------------
extern "C" void kernel_launch(void* const* d_in, const int* in_sizes, int n_in,
                              void* d_out, int out_size)
{
    const int*   tk = (const int*)  d_in[0];   // spike_ticks
    const int*   xs = (const int*)  d_in[1];   // spike_x
    const int*   ys = (const int*)  d_in[2];   // spike_y
    const float* vs = (const float*)d_in[3];   // spike_values
    const float* w  = (const float*)d_in[4];   // weights [128,49]
    const int*   sp = (const int*)  d_in[5];   // stride
    const int    n  = in_sizes[0];

    void* hist_ptr = nullptr;
    cudaGetSymbolAddress(&hist_ptr, d_hist);
    cudaMemsetAsync(hist_ptr, 0, sizeof(float) * MAXC * TICKS);   // memset node

    scatter_kernel<<<148, 1024>>>(tk, xs, ys, vs, sp, n);
    sim_kernel<<<OUT_CH, 1024>>>(w, sp, (float*)d_out);
}

// round 8
// speedup vs baseline: 2.0576x; 1.5361x over previous
#include <cuda_runtime.h>
#include <cuda_bf16.h>

#define TICKS   1000
#define TPAD    1024        // TICKS rounded up to 32 — sim chunks read the pad
#define NTAPS   49
#define KW      7
#define OUT_CH  128
#define MAXD    14          // 6 + min(stride,8)
#define MAXC    (MAXD*MAXD) // 196

// ---- scratch (no allocations allowed) ----
// Transposed layout: hist[cls][t] -> warp-coalesced loads over t in sim Phase B.
__device__ __align__(16) float d_hist[MAXC * TICKS];

__device__ __forceinline__ int imin(int a, int b) { return a < b ? a : b; }

// ------------------------------------------------------------------
// 1) event scatter into hist[cls][t].
//    stride==2 fast path: the 4 hot classes (x>=6 && y>=6, 91% of events)
//    aggregate in shared memory (ATOMS ~2cyc/lane vs REDG ~1.29cyc/lane x
//    LSU queue share), flushed once per CTA. Cold events + generic strides
//    go straight to L2 via RED.F32 (no return -> no scoreboard stalls).
//    spike_values are 1.0f so per-slot sums are exact integers: atomic
//    ordering cannot perturb results.
// ------------------------------------------------------------------
__global__ void __launch_bounds__(1024) scatter_kernel(
    const int* __restrict__ tk, const int* __restrict__ xs,
    const int* __restrict__ ys, const float* __restrict__ vs,
    const int* __restrict__ sp, int n)
{
    __shared__ float sh[4 * 1024];             // [hot][t], t padded to 1024
    const int stride = *sp;
    const int D  = 6 + imin(stride, 8);
    const bool s2 = (stride == 2);

    if (s2) {
        for (int i = threadIdx.x; i < 4 * 1024; i += blockDim.x) sh[i] = 0.f;
        __syncthreads();
    }

    const int tid = blockIdx.x * blockDim.x + threadIdx.x;
    const int nth = gridDim.x * blockDim.x;

    auto proc = [&](int t, int x, int y, float v) {
        if (s2) {                                // warp-uniform branch
            if (x >= 6 && y >= 6) {              // hot: smem ATOMS
                int h = ((y & 1) << 1) | (x & 1);
                atomicAdd(&sh[h * 1024 + t], v);
            } else {                             // cold (~9%): global RED
                int cx = (x < 6) ? x : 6 + (x & 1);
                int cy = (y < 6) ? y : 6 + (y & 1);
                atomicAdd(&d_hist[(cy * 8 + cx) * TICKS + t], v);
            }
        } else {
            int cx = (x < 6) ? x : 6 + imin(x % stride, 7);
            int cy = (y < 6) ? y : 6 + imin(y % stride, 7);
            atomicAdd(&d_hist[(cy * D + cx) * TICKS + t], v);
        }
    };

    const int n4 = n >> 2;
    const int4*   t4 = reinterpret_cast<const int4*>(tk);
    const int4*   x4 = reinterpret_cast<const int4*>(xs);
    const int4*   y4 = reinterpret_cast<const int4*>(ys);
    const float4* v4 = reinterpret_cast<const float4*>(vs);

    for (int i = tid; i < n4; i += nth) {
        int4   a = t4[i];
        int4   b = x4[i];
        int4   c = y4[i];
        float4 w = v4[i];
        proc(a.x, b.x, c.x, w.x);
        proc(a.y, b.y, c.y, w.y);
        proc(a.z, b.z, c.z, w.z);
        proc(a.w, b.w, c.w, w.w);
    }
    for (int i = (n4 << 2) + tid; i < n; i += nth)
        proc(tk[i], xs[i], ys[i], vs[i]);

    if (s2) {
        __syncthreads();
        // flush hot classes: stride=2 -> D=8, cls = (6+ry)*8 + (6+rx) = 54+8ry+rx
        for (int i = threadIdx.x; i < 4 * TICKS; i += blockDim.x) {
            int h = i / TICKS, t = i - h * TICKS;
            float val = sh[h * 1024 + t];
            if (val != 0.f) {
                int cls = 54 + 8 * (h >> 1) + (h & 1);
                atomicAdd(&d_hist[cls * TICKS + t], val);
            }
        }
    }
}

// ------------------------------------------------------------------
// 2) fused drive + Izhikevich sim. One 1024-thread block per channel.
//    Phase A: class weights (shared).
//    Phase B: one tick per thread — warp lanes read consecutive t of the
//             same hist row (coalesced LDG.32). Single sequential
//             accumulator over cls (unchanged order -> bit-identical g).
//    Phase C: warp 0 runs the serial recurrence. Spike reset via ternary
//             selects (FSEL, pred-as-data 4cyc) instead of predicated
//             guard (13cyc) — selection only, bit-identical output.
// ------------------------------------------------------------------
__global__ void __launch_bounds__(1024) sim_kernel(
    const float* __restrict__ w, const int* __restrict__ sp,
    float* __restrict__ out)
{
    __shared__ float wc[MAXC];
    __shared__ float sg[TPAD + 4];

    const int c   = blockIdx.x;
    const int tid = threadIdx.x;
    const int stride = *sp;
    const int D = 6 + imin(stride, 8);
    const int C = D * D;

    // ---- Phase A: class weights for this channel ----
    if (tid < C) {
        const int cls = tid;
        const int cy = cls / D, cx = cls % D;
        int sx, lx, sy, ly;
        if (cx < 6) { sx = cx % stride; lx = cx; } else { sx = cx - 6; lx = 6; }
        if (cy < 6) { sy = cy % stride; ly = cy; } else { sy = cy - 6; ly = 6; }
        float acc = 0.f;
        for (int ky = sy; ky <= ly; ky += stride)
            for (int kx = sx; kx <= lx; kx += stride)
                acc += w[c * NTAPS + ky * KW + kx];
        wc[cls] = acc;
    }
    // zero sg (covers sg[0] and the pad)
    for (int i = tid; i < TPAD + 4; i += blockDim.x) sg[i] = 0.f;
    __syncthreads();

    // ---- Phase B: sg[t] = dot(wc, hist[:, t-1]) for t in [1, TICKS] ----
    if (tid >= 1 && tid <= TICKS) {
        const int tm1 = tid - 1;                  // source tick
        const float* __restrict__ hp = d_hist + tm1;
        float acc = 0.f;
        #pragma unroll 16
        for (int cls = 0; cls < C; ++cls)
            acc = fmaf(wc[cls], __ldg(&hp[cls * TICKS]), acc);
        sg[tid] = acc;                            // 1-tick synaptic delay
    }
    __syncthreads();

    // ---- Phase C: serial sim, warp 0 only ----
    if (tid >= 32) return;
    const int lane = tid;

    float* __restrict__ ospk = out + c * TICKS;
    float* __restrict__ ovtr = out + OUT_CH * TICKS + c * TICKS;

    const float decay = 0.9f;                        // 1 - dt/tau_fall
    const float h     = (float)(0.001 / 150.0);      // dt / C
    const float Kp = 1.2f, VR = -75.f, VT = -45.f;
    const float AP = 0.01f, BP = 5.f, VP = 50.f;
    const float DP = 130.f, VRS = -56.f, IIN = 350.f, DT = 0.001f;

    float v = VR, u = 0.f, S = 0.f;

    for (int t0 = 0; t0 < TICKS; t0 += 32) {
        float keepv = 0.f, keeps = 0.f;
        #pragma unroll
        for (int i = 0; i < 32; ++i) {
            float gt = sg[t0 + i];                   // pad ticks harmless
            S = S * decay + gt;                      // summed synapse state
            float I = IIN + S;                       // I_bias = 0
            v = v + (Kp * (v - VR) * (v - VT) - u + I) * h;
            float unew = u + AP * (BP * (v - VR) - u) * DT;  // pre-reset v
            bool sp_ = v >= VP;
            float spf = sp_ ? 1.f : 0.f;             // FSEL (pred-as-data)
            v = sp_ ? VRS : v;                       // FSEL: 4cyc, not @P 13cyc
            u = sp_ ? unew + DP : unew;              // same FADDs, select only
            keepv = (lane == i) ? v   : keepv;       // register-keep, off chain
            keeps = (lane == i) ? spf : keeps;
        }
        int t = t0 + lane;
        if (t < TICKS) {                             // guard: 1000 % 32 != 0
            ospk[t] = keeps;                         // coalesced per chunk
            ovtr[t] = keepv;
        }
    }
}

// ------------------------------------------------------------------
extern "C" void kernel_launch(void* const* d_in, const int* in_sizes, int n_in,
                              void* d_out, int out_size)
{
    const int*   tk = (const int*)  d_in[0];   // spike_ticks
    const int*   xs = (const int*)  d_in[1];   // spike_x
    const int*   ys = (const int*)  d_in[2];   // spike_y
    const float* vs = (const float*)d_in[3];   // spike_values
    const float* w  = (const float*)d_in[4];   // weights [128,49]
    const int*   sp = (const int*)  d_in[5];   // stride
    const int    n  = in_sizes[0];

    void* hist_ptr = nullptr;
    cudaGetSymbolAddress(&hist_ptr, d_hist);
    cudaMemsetAsync(hist_ptr, 0, sizeof(float) * MAXC * TICKS);   // memset node

    scatter_kernel<<<148, 1024>>>(tk, xs, ys, vs, sp, n);
    sim_kernel<<<OUT_CH, 1024>>>(w, sp, (float*)d_out);
}

// round 9
// speedup vs baseline: 2.2956x; 1.1157x over previous
#include <cuda_runtime.h>
#include <cuda_bf16.h>

#define TICKS   1000
#define TPAD    1024        // TICKS rounded up to 32 — sim chunks read the pad
#define NTAPS   49
#define KW      7
#define OUT_CH  128
#define MAXD    14          // 6 + min(stride,8)
#define MAXC    (MAXD*MAXD) // 196

// ---- scratch (no allocations allowed) ----
// Transposed layout: hist[cls][t] -> warp-coalesced loads over t in sim Phase B.
__device__ __align__(16) float d_hist[MAXC * TICKS];

__device__ __forceinline__ int imin(int a, int b) { return a < b ? a : b; }

// ------------------------------------------------------------------
// 1) event scatter into hist[cls][t].
//    stride==2 fast path: the 4 hot classes (x>=6 && y>=6, 91% of events)
//    aggregate in shared memory (ATOMS), flushed once per CTA. Cold events
//    + generic strides go straight to L2 via RED.F32 (no return -> no
//    scoreboard stalls). spike_values are 1.0f so per-slot sums are exact
//    integers: atomic ordering cannot perturb results.
// ------------------------------------------------------------------
__global__ void __launch_bounds__(1024) scatter_kernel(
    const int* __restrict__ tk, const int* __restrict__ xs,
    const int* __restrict__ ys, const float* __restrict__ vs,
    const int* __restrict__ sp, int n)
{
    __shared__ float sh[4 * 1024];             // [hot][t], t padded to 1024
    const int stride = *sp;
    const int D  = 6 + imin(stride, 8);
    const bool s2 = (stride == 2);

    if (s2) {
        for (int i = threadIdx.x; i < 4 * 1024; i += blockDim.x) sh[i] = 0.f;
        __syncthreads();
    }

    const int tid = blockIdx.x * blockDim.x + threadIdx.x;
    const int nth = gridDim.x * blockDim.x;

    auto proc = [&](int t, int x, int y, float v) {
        if (s2) {                                // warp-uniform branch
            if (x >= 6 && y >= 6) {              // hot: smem ATOMS
                int h = ((y & 1) << 1) | (x & 1);
                atomicAdd(&sh[h * 1024 + t], v);
            } else {                             // cold (~9%): global RED
                int cx = (x < 6) ? x : 6 + (x & 1);
                int cy = (y < 6) ? y : 6 + (y & 1);
                atomicAdd(&d_hist[(cy * 8 + cx) * TICKS + t], v);
            }
        } else {
            int cx = (x < 6) ? x : 6 + imin(x % stride, 7);
            int cy = (y < 6) ? y : 6 + imin(y % stride, 7);
            atomicAdd(&d_hist[(cy * D + cx) * TICKS + t], v);
        }
    };

    const int n4 = n >> 2;
    const int4*   t4 = reinterpret_cast<const int4*>(tk);
    const int4*   x4 = reinterpret_cast<const int4*>(xs);
    const int4*   y4 = reinterpret_cast<const int4*>(ys);
    const float4* v4 = reinterpret_cast<const float4*>(vs);

    for (int i = tid; i < n4; i += nth) {
        int4   a = t4[i];
        int4   b = x4[i];
        int4   c = y4[i];
        float4 w = v4[i];
        proc(a.x, b.x, c.x, w.x);
        proc(a.y, b.y, c.y, w.y);
        proc(a.z, b.z, c.z, w.z);
        proc(a.w, b.w, c.w, w.w);
    }
    for (int i = (n4 << 2) + tid; i < n; i += nth)
        proc(tk[i], xs[i], ys[i], vs[i]);

    if (s2) {
        __syncthreads();
        // flush hot classes: stride=2 -> D=8, cls = (6+ry)*8 + (6+rx) = 54+8ry+rx
        for (int i = threadIdx.x; i < 4 * TICKS; i += blockDim.x) {
            int h = i / TICKS, t = i - h * TICKS;
            float val = sh[h * 1024 + t];
            if (val != 0.f) {
                int cls = 54 + 8 * (h >> 1) + (h & 1);
                atomicAdd(&d_hist[cls * TICKS + t], val);
            }
        }
    }
}

// ------------------------------------------------------------------
// 2) fused drive + Izhikevich sim. One 1024-thread block per channel.
//    Phase A: class weights (shared).
//    Phase B: one tick per thread — warp lanes read consecutive t of the
//             same hist row (coalesced LDG.32). Single sequential
//             accumulator over cls (unchanged order -> bit-identical g).
//    Phase C: warp 0, serial recurrence with THRESHOLD SPECULATION:
//             both next-v candidates computed before the spike predicate
//             resolves; the spiked candidate chains from the constant
//             VRESET (Kp*(VRS-VR)*(VRS-VT) folds at compile time under
//             the same IEEE-RN rounding as the runtime ops). Per-path
//             arithmetic identical to the reference path -> bit-identical.
//             Chain: FSEL+FADD+2xFMUL+2xFADD+FFMA = ~28cyc/tick; FSETP
//             (13cyc pred production) hidden in the chain's shadow.
// ------------------------------------------------------------------
__global__ void __launch_bounds__(1024) sim_kernel(
    const float* __restrict__ w, const int* __restrict__ sp,
    float* __restrict__ out)
{
    __shared__ float wc[MAXC];
    __shared__ float sg[TPAD + 4];

    const int c   = blockIdx.x;
    const int tid = threadIdx.x;
    const int stride = *sp;
    const int D = 6 + imin(stride, 8);
    const int C = D * D;

    // ---- Phase A: class weights for this channel ----
    if (tid < C) {
        const int cls = tid;
        const int cy = cls / D, cx = cls % D;
        int sx, lx, sy, ly;
        if (cx < 6) { sx = cx % stride; lx = cx; } else { sx = cx - 6; lx = 6; }
        if (cy < 6) { sy = cy % stride; ly = cy; } else { sy = cy - 6; ly = 6; }
        float acc = 0.f;
        for (int ky = sy; ky <= ly; ky += stride)
            for (int kx = sx; kx <= lx; kx += stride)
                acc += w[c * NTAPS + ky * KW + kx];
        wc[cls] = acc;
    }
    // zero sg (covers sg[0] and the pad)
    for (int i = tid; i < TPAD + 4; i += blockDim.x) sg[i] = 0.f;
    __syncthreads();

    // ---- Phase B: sg[t] = dot(wc, hist[:, t-1]) for t in [1, TICKS] ----
    if (tid >= 1 && tid <= TICKS) {
        const int tm1 = tid - 1;                  // source tick
        const float* __restrict__ hp = d_hist + tm1;
        float acc = 0.f;
        #pragma unroll 16
        for (int cls = 0; cls < C; ++cls)
            acc = fmaf(wc[cls], __ldg(&hp[cls * TICKS]), acc);
        sg[tid] = acc;                            // 1-tick synaptic delay
    }
    __syncthreads();

    // ---- Phase C: serial sim, warp 0 only ----
    if (tid >= 32) return;
    const int lane = tid;

    float* __restrict__ ospk = out + c * TICKS;
    float* __restrict__ ovtr = out + OUT_CH * TICKS + c * TICKS;

    const float decay = 0.9f;                        // 1 - dt/tau_fall
    const float h     = (float)(0.001 / 150.0);      // dt / C
    const float Kp = 1.2f, VR = -75.f, VT = -45.f;
    const float AP = 0.01f, BP = 5.f, VP = 50.f;
    const float DP = 130.f, VRS = -56.f, IIN = 350.f, DT = 0.001f;
    // constant-folded spike-path product: Kp*(VRS-VR)*(VRS-VT), same RN
    // rounding the runtime FADD/FMULs produce (19 and -11 are exact).
    const float QC = 1.2f * (VRS - VR) * (VRS - VT);

    // carry: vpre = v BEFORE reset of previous tick; spprev = its spike bit.
    // init equivalent to v_post = VREST, no prior spike.
    float vpre = VR, u = 0.f, S = 0.f;
    bool  spprev = false;

    for (int t0 = 0; t0 < TICKS; t0 += 32) {
        float keepv = 0.f, keeps = 0.f;
        #pragma unroll
        for (int i = 0; i < 32; ++i) {
            float gt = sg[t0 + i];                   // pad ticks harmless
            S = S * decay + gt;                      // summed synapse state
            float I = IIN + S;                       // I_bias = 0
            // both candidates, computed before spprev's select:
            float vn  = vpre + (Kp * (vpre - VR) * (vpre - VT) - u + I) * h;
            float vsp = VRS  + (QC - u + I) * h;     // chains via u,I only
            float vnew = spprev ? vsp : vn;          // FSEL (pred long ready)
            // u update uses pre-reset v (reference order)
            float unew = u + AP * (BP * (vnew - VR) - u) * DT;
            bool sp_ = vnew >= VP;                   // FSETP off-chain now
            float spf   = sp_ ? 1.f : 0.f;
            float vpost = sp_ ? VRS : vnew;          // output value only
            u = sp_ ? unew + DP : unew;
            vpre = vnew; spprev = sp_;
            keepv = (lane == i) ? vpost : keepv;     // register-keep, off chain
            keeps = (lane == i) ? spf   : keeps;
        }
        int t = t0 + lane;
        if (t < TICKS) {                             // guard: 1000 % 32 != 0
            ospk[t] = keeps;                         // coalesced per chunk
            ovtr[t] = keepv;
        }
    }
}

// ------------------------------------------------------------------
extern "C" void kernel_launch(void* const* d_in, const int* in_sizes, int n_in,
                              void* d_out, int out_size)
{
    const int*   tk = (const int*)  d_in[0];   // spike_ticks
    const int*   xs = (const int*)  d_in[1];   // spike_x
    const int*   ys = (const int*)  d_in[2];   // spike_y
    const float* vs = (const float*)d_in[3];   // spike_values
    const float* w  = (const float*)d_in[4];   // weights [128,49]
    const int*   sp = (const int*)  d_in[5];   // stride
    const int    n  = in_sizes[0];

    void* hist_ptr = nullptr;
    cudaGetSymbolAddress(&hist_ptr, d_hist);
    cudaMemsetAsync(hist_ptr, 0, sizeof(float) * MAXC * TICKS);   // memset node

    scatter_kernel<<<148, 1024>>>(tk, xs, ys, vs, sp, n);
    sim_kernel<<<OUT_CH, 1024>>>(w, sp, (float*)d_out);
}